// round 6
// baseline (speedup 1.0000x reference)
#include <cuda_runtime.h>
#include <math.h>
#include <stdint.h>

// Problem constants
#define NDIM 8192
#define HDIM 512
#define TAU_INV 2.0f     // 1/0.5
#define EPSV 1e-8f

// MLP tiling (unchanged from R5)
constexpr int BM = 128, BN = 128, BK = 32;
constexpr int NTHREADS = 256;

// Sim tiling: block 128x256, 8 warps (2m x 4n), warp tile 64x64, double-buffered
constexpr int SBM = 128, SBN = 256, SBK = 32;
constexpr int S_A_WORDS = 4096;   // 128x32 tf32 per stage
constexpr int S_B_WORDS = 8192;   // 256x32 tf32 per stage
constexpr int S_SMEM_BYTES = (2 * S_A_WORDS + 2 * S_B_WORDS) * 4 + 2 * SBM * 4;

// Scratch (static device memory; no allocation allowed)
__device__ float g_h[2ull * NDIM * HDIM];   // hidden activations (32 MB)
__device__ float g_inv0[NDIM];
__device__ float g_inv1[NDIM];
__device__ float g_S[NDIM];
__device__ float g_P[NDIM];

__device__ __forceinline__ uint32_t f2tf32(float f) {
    uint32_t u;
    asm("cvt.rna.tf32.f32 %0, %1;" : "=r"(u) : "f"(f));
    return u;
}

__device__ __forceinline__ void mma_tf32(float c[4],
                                         const uint32_t a[4],
                                         const uint32_t b[2]) {
    asm volatile(
        "mma.sync.aligned.m16n8k8.row.col.f32.tf32.tf32.f32 "
        "{%0,%1,%2,%3}, {%4,%5,%6,%7}, {%8,%9}, {%0,%1,%2,%3};"
        : "+f"(c[0]), "+f"(c[1]), "+f"(c[2]), "+f"(c[3])
        : "r"(a[0]), "r"(a[1]), "r"(a[2]), "r"(a[3]),
          "r"(b[0]), "r"(b[1]));
}

// ---------------------------------------------------------------------------
// MLP fragment-ordered smem fill (128x32 A, 128x32 B) — unchanged from R5.
// ---------------------------------------------------------------------------
__device__ __forceinline__ void fill_tiles(
    uint32_t* sA, uint32_t* sB,
    const float* __restrict__ A, const float* __restrict__ B,
    int rowBase, int colBase, int K, int k0, int t)
{
#pragma unroll
    for (int v = 0; v < 4; v++) {
        int idx = t + v * 256;
        int row = idx >> 3;
        int q   = idx & 7;
        int ks  = q >> 1;
        int e2  = q & 1;

        float4 va = *reinterpret_cast<const float4*>(
            &A[(size_t)(rowBase + row) * K + k0 + (q << 2)]);
        {
            int mt = row >> 4;
            int rr = row & 15;
            int r  = (rr >> 3) + (e2 << 1);
            uint32_t* p = &sA[(((((mt << 2) + ks) << 5) + ((rr & 7) << 2)) << 2) + r];
            p[0]  = f2tf32(va.x);
            p[4]  = f2tf32(va.y);
            p[8]  = f2tf32(va.z);
            p[12] = f2tf32(va.w);
        }
        float4 vb = *reinterpret_cast<const float4*>(
            &B[(size_t)(colBase + row) * K + k0 + (q << 2)]);
        {
            int nt = row >> 3;
            uint32_t* p = &sB[((((((nt << 2) + ks) << 5) + ((row & 7) << 2))) << 1) + e2];
            p[0] = f2tf32(vb.x);
            p[2] = f2tf32(vb.y);
            p[4] = f2tf32(vb.z);
            p[6] = f2tf32(vb.w);
        }
    }
}

// ---------------------------------------------------------------------------
// MLP GEMM: C = act(A @ B^T + bias), tf32 tensor cores (unchanged from R5).
// ---------------------------------------------------------------------------
__global__ __launch_bounds__(NTHREADS) void gemm_bias_act_mma(
    const float* __restrict__ A0, const float* __restrict__ A1,
    const float* __restrict__ B, const float* __restrict__ bias,
    float* __restrict__ C0, float* __restrict__ C1,
    int K, int Nn, int doElu)
{
    __shared__ uint32_t sA[4096];
    __shared__ uint32_t sB[4096];

    const float* A = (blockIdx.z == 0) ? A0 : A1;
    float* C = (blockIdx.z == 0) ? C0 : C1;

    const int t = threadIdx.x;
    const int wid = t >> 5, lane = t & 31;
    const int wm = wid >> 2, wn = wid & 3;
    const int rowBase = blockIdx.y * BM;
    const int colBase = blockIdx.x * BN;

    float acc[4][4][4];
#pragma unroll
    for (int i = 0; i < 4; i++)
#pragma unroll
        for (int j = 0; j < 4; j++)
#pragma unroll
            for (int r = 0; r < 4; r++) acc[i][j][r] = 0.0f;

    for (int k0 = 0; k0 < K; k0 += BK) {
        fill_tiles(sA, sB, A, B, rowBase, colBase, K, k0, t);
        __syncthreads();

#pragma unroll
        for (int ks = 0; ks < 4; ks++) {
            uint32_t af[4][4];
            uint32_t bf[4][2];
#pragma unroll
            for (int am = 0; am < 4; am++) {
                uint4 v = *reinterpret_cast<const uint4*>(
                    &sA[(((((wm << 2) + am) << 2) + ks) << 5 | lane) << 2]);
                af[am][0] = v.x; af[am][1] = v.y; af[am][2] = v.z; af[am][3] = v.w;
            }
#pragma unroll
            for (int bn = 0; bn < 4; bn++) {
                uint2 v = *reinterpret_cast<const uint2*>(
                    &sB[(((((wn << 2) + bn) << 2) + ks) << 5 | lane) << 1]);
                bf[bn][0] = v.x; bf[bn][1] = v.y;
            }
#pragma unroll
            for (int am = 0; am < 4; am++)
#pragma unroll
                for (int bn = 0; bn < 4; bn++)
                    mma_tf32(acc[am][bn], af[am], bf[bn]);
        }
        __syncthreads();
    }

#pragma unroll
    for (int am = 0; am < 4; am++) {
        int row0 = rowBase + wm * 64 + am * 16 + (lane >> 2);
#pragma unroll
        for (int bn = 0; bn < 4; bn++) {
            int col = colBase + wn * 32 + bn * 8 + ((lane & 3) << 1);
            float b0 = bias[col], b1 = bias[col + 1];
            float v0 = acc[am][bn][0] + b0;
            float v1 = acc[am][bn][1] + b1;
            float v2 = acc[am][bn][2] + b0;
            float v3 = acc[am][bn][3] + b1;
            if (doElu) {
                v0 = (v0 > 0.0f) ? v0 : expm1f(v0);
                v1 = (v1 > 0.0f) ? v1 : expm1f(v1);
                v2 = (v2 > 0.0f) ? v2 : expm1f(v2);
                v3 = (v3 > 0.0f) ? v3 : expm1f(v3);
            }
            float2 lo = {v0, v1}, hi = {v2, v3};
            *reinterpret_cast<float2*>(&C[(size_t)row0 * Nn + col]) = lo;
            *reinterpret_cast<float2*>(&C[(size_t)(row0 + 8) * Nn + col]) = hi;
        }
    }
}

// ---------------------------------------------------------------------------
// Row norms (inverse) + zero the S/P accumulators.
// ---------------------------------------------------------------------------
__global__ void norm_init_kernel(const float* __restrict__ z0,
                                 const float* __restrict__ z1)
{
    int b = blockIdx.x;
    int row = (b < NDIM) ? b : (b - NDIM);
    const float* z = (b < NDIM) ? z0 : z1;

    float4 v = *reinterpret_cast<const float4*>(
        &z[(size_t)row * HDIM + threadIdx.x * 4]);
    float ss = v.x * v.x + v.y * v.y + v.z * v.z + v.w * v.w;
#pragma unroll
    for (int off = 16; off; off >>= 1)
        ss += __shfl_xor_sync(0xffffffffu, ss, off);

    __shared__ float sred[4];
    if ((threadIdx.x & 31) == 0) sred[threadIdx.x >> 5] = ss;
    __syncthreads();
    if (threadIdx.x == 0) {
        float tot = sred[0] + sred[1] + sred[2] + sred[3];
        float inv = 1.0f / sqrtf(tot);
        if (b < NDIM) {
            g_inv0[row] = inv;
            g_S[row] = 0.0f;
            g_P[row] = 0.0f;
        } else {
            g_inv1[row] = inv;
        }
    }
}

// ---------------------------------------------------------------------------
// Fused similarity: block 128x256, warp tile 64x64, double-buffered smem,
// one __syncthreads per k-iter. Epilogue: exp(cos/tau) -> per-row S/P sums.
// ---------------------------------------------------------------------------
__global__ __launch_bounds__(NTHREADS, 1) void sim_fused_mma(
    const float* __restrict__ z0, const float* __restrict__ z1,
    const float* __restrict__ pos)
{
    extern __shared__ uint32_t dynsmem[];
    uint32_t* sA = dynsmem;                         // [2][S_A_WORDS]
    uint32_t* sB = dynsmem + 2 * S_A_WORDS;         // [2][S_B_WORDS]
    float* sS = (float*)(dynsmem + 2 * S_A_WORDS + 2 * S_B_WORDS);
    float* sP = sS + SBM;

    const int t = threadIdx.x;
    const int wid = t >> 5, lane = t & 31;
    const int wm = wid >> 2, wn = wid & 3;          // wm in {0,1}, wn in {0..3}
    const int rowBase = blockIdx.y * SBM;
    const int colBase = blockIdx.x * SBN;
    const int K = HDIM;

    if (t < SBM) { sS[t] = 0.0f; sP[t] = 0.0f; }

    // --- hoisted fill addressing (loop-invariant) ---
    uint32_t offA[4];  const float* gA[4];
    uint32_t offB[8];  const float* gB[8];
#pragma unroll
    for (int v = 0; v < 4; v++) {
        int idx = t + v * 256;
        int row = idx >> 3;
        int q   = idx & 7;
        int ks  = q >> 1;
        int e2  = q & 1;
        int mt = row >> 4;
        int rr = row & 15;
        int r  = (rr >> 3) + (e2 << 1);
        offA[v] = ((((((mt << 2) + ks) << 5) + ((rr & 7) << 2))) << 2) + r;
        gA[v] = &z0[(size_t)(rowBase + row) * K + (q << 2)];
    }
#pragma unroll
    for (int v = 0; v < 8; v++) {
        int idx = t + v * 256;
        int row = idx >> 3;                          // 0..255
        int q   = idx & 7;
        int ks  = q >> 1;
        int e2  = q & 1;
        int nt  = row >> 3;
        offB[v] = ((((((nt << 2) + ks) << 5) + ((row & 7) << 2))) << 1) + e2;
        gB[v] = &z1[(size_t)(colBase + row) * K + (q << 2)];
    }

    float acc[4][8][4];
#pragma unroll
    for (int i = 0; i < 4; i++)
#pragma unroll
        for (int j = 0; j < 8; j++)
#pragma unroll
            for (int r = 0; r < 4; r++) acc[i][j][r] = 0.0f;

    // --- fill stage 0 ---
    {
        uint32_t* dA = sA;
        uint32_t* dB = sB;
#pragma unroll
        for (int v = 0; v < 4; v++) {
            float4 va = *reinterpret_cast<const float4*>(gA[v]);
            uint32_t* p = &dA[offA[v]];
            p[0] = f2tf32(va.x); p[4] = f2tf32(va.y);
            p[8] = f2tf32(va.z); p[12] = f2tf32(va.w);
        }
#pragma unroll
        for (int v = 0; v < 8; v++) {
            float4 vb = *reinterpret_cast<const float4*>(gB[v]);
            uint32_t* p = &dB[offB[v]];
            p[0] = f2tf32(vb.x); p[2] = f2tf32(vb.y);
            p[4] = f2tf32(vb.z); p[6] = f2tf32(vb.w);
        }
    }
    __syncthreads();

    const int NITER = K / SBK;   // 16
    for (int it = 0; it < NITER; it++) {
        const int cur = it & 1;
        const uint32_t* cA = sA + cur * S_A_WORDS;
        const uint32_t* cB = sB + cur * S_B_WORDS;

        // Prefetch+store next stage (different buffer; no hazard with cur reads)
        if (it + 1 < NITER) {
            const int k0n = (it + 1) * SBK;
            uint32_t* dA = sA + (cur ^ 1) * S_A_WORDS;
            uint32_t* dB = sB + (cur ^ 1) * S_B_WORDS;
#pragma unroll
            for (int v = 0; v < 4; v++) {
                float4 va = *reinterpret_cast<const float4*>(gA[v] + k0n);
                uint32_t* p = &dA[offA[v]];
                p[0] = f2tf32(va.x); p[4] = f2tf32(va.y);
                p[8] = f2tf32(va.z); p[12] = f2tf32(va.w);
            }
#pragma unroll
            for (int v = 0; v < 8; v++) {
                float4 vb = *reinterpret_cast<const float4*>(gB[v] + k0n);
                uint32_t* p = &dB[offB[v]];
                p[0] = f2tf32(vb.x); p[2] = f2tf32(vb.y);
                p[4] = f2tf32(vb.z); p[6] = f2tf32(vb.w);
            }
        }

#pragma unroll
        for (int ks = 0; ks < 4; ks++) {
            uint32_t af[4][4];
            uint32_t bf[8][2];
#pragma unroll
            for (int am = 0; am < 4; am++) {
                uint4 v = *reinterpret_cast<const uint4*>(
                    &cA[((((((wm << 2) + am) << 2) + ks) << 5) | lane) << 2]);
                af[am][0] = v.x; af[am][1] = v.y; af[am][2] = v.z; af[am][3] = v.w;
            }
#pragma unroll
            for (int bn = 0; bn < 8; bn++) {
                uint2 v = *reinterpret_cast<const uint2*>(
                    &cB[((((((wn << 3) + bn) << 2) + ks) << 5) | lane) << 1]);
                bf[bn][0] = v.x; bf[bn][1] = v.y;
            }
#pragma unroll
            for (int am = 0; am < 4; am++)
#pragma unroll
                for (int bn = 0; bn < 8; bn++)
                    mma_tf32(acc[am][bn], af[am], bf[bn]);
        }
        __syncthreads();
    }

    // Epilogue: exp(cos/tau), weight by pos, per-row reduce
#pragma unroll
    for (int am = 0; am < 4; am++) {
        int rloc0 = wm * 64 + am * 16 + (lane >> 2);
        int row0 = rowBase + rloc0;
        float ii0 = g_inv0[row0] * TAU_INV;
        float ii1 = g_inv0[row0 + 8] * TAU_INV;
        float s0 = 0.0f, p0 = 0.0f, s1 = 0.0f, p1 = 0.0f;
#pragma unroll
        for (int bn = 0; bn < 8; bn++) {
            int col = colBase + wn * 64 + bn * 8 + ((lane & 3) << 1);
            float j0 = g_inv1[col];
            float j1 = g_inv1[col + 1];
            float2 pv0 = *reinterpret_cast<const float2*>(
                &pos[(size_t)row0 * NDIM + col]);
            float2 pv1 = *reinterpret_cast<const float2*>(
                &pos[(size_t)(row0 + 8) * NDIM + col]);
            float m;
            m = expf(acc[am][bn][0] * ii0 * j0); s0 += m; p0 += m * pv0.x;
            m = expf(acc[am][bn][1] * ii0 * j1); s0 += m; p0 += m * pv0.y;
            m = expf(acc[am][bn][2] * ii1 * j0); s1 += m; p1 += m * pv1.x;
            m = expf(acc[am][bn][3] * ii1 * j1); s1 += m; p1 += m * pv1.y;
        }
#pragma unroll
        for (int off = 1; off < 4; off <<= 1) {
            s0 += __shfl_xor_sync(0xffffffffu, s0, off);
            p0 += __shfl_xor_sync(0xffffffffu, p0, off);
            s1 += __shfl_xor_sync(0xffffffffu, s1, off);
            p1 += __shfl_xor_sync(0xffffffffu, p1, off);
        }
        if ((lane & 3) == 0) {
            atomicAdd(&sS[rloc0], s0);
            atomicAdd(&sP[rloc0], p0);
            atomicAdd(&sS[rloc0 + 8], s1);
            atomicAdd(&sP[rloc0 + 8], p1);
        }
    }
    __syncthreads();
    if (t < SBM) {
        atomicAdd(&g_S[rowBase + t], sS[t]);
        atomicAdd(&g_P[rowBase + t], sP[t]);
    }
}

// ---------------------------------------------------------------------------
// Final loss: -mean(log(P/(S+eps)+eps))
// ---------------------------------------------------------------------------
__global__ void loss_kernel(float* __restrict__ loss_out)
{
    float local = 0.0f;
    for (int i = threadIdx.x; i < NDIM; i += 256) {
        local += logf(g_P[i] / (g_S[i] + EPSV) + EPSV);
    }
#pragma unroll
    for (int off = 16; off; off >>= 1)
        local += __shfl_xor_sync(0xffffffffu, local, off);

    __shared__ float sred[8];
    if ((threadIdx.x & 31) == 0) sred[threadIdx.x >> 5] = local;
    __syncthreads();
    if (threadIdx.x == 0) {
        float tot = 0.0f;
#pragma unroll
        for (int w = 0; w < 8; w++) tot += sred[w];
        loss_out[0] = -tot / (float)NDIM;
    }
}

// ---------------------------------------------------------------------------
// kernel_launch — inputs: embd0, embd1, pos, W1, b1, W2, b2
// output layout: [z0 (N*H) | z1 (N*H) | loss (1)]
// ---------------------------------------------------------------------------
extern "C" void kernel_launch(void* const* d_in, const int* in_sizes, int n_in,
                              void* d_out, int out_size)
{
    const float* embd0 = (const float*)d_in[0];
    const float* embd1 = (const float*)d_in[1];
    const float* pos   = (const float*)d_in[2];
    const float* W1    = (const float*)d_in[3];
    const float* b1    = (const float*)d_in[4];
    const float* W2    = (const float*)d_in[5];
    const float* b2    = (const float*)d_in[6];

    float* out = (float*)d_out;
    float* z0 = out;
    float* z1 = out + (size_t)NDIM * HDIM;
    float* loss = out + 2ull * NDIM * HDIM;

    float* h = nullptr;
    cudaGetSymbolAddress((void**)&h, g_h);
    float* h0 = h;
    float* h1 = h + (size_t)NDIM * HDIM;

    static bool attrDone = false;
    if (!attrDone) {
        cudaFuncSetAttribute(sim_fused_mma,
                             cudaFuncAttributeMaxDynamicSharedMemorySize,
                             S_SMEM_BYTES);
        attrDone = true;
    }

    dim3 blk(NTHREADS);
    dim3 grid_mlp(HDIM / BN, NDIM / BM, 2);     // 4 x 64 x 2
    dim3 grid_sim(NDIM / SBN, NDIM / SBM);      // 32 x 64

    gemm_bias_act_mma<<<grid_mlp, blk>>>(embd0, embd1, W1, b1, h0, h1,
                                         HDIM, HDIM, 1);
    gemm_bias_act_mma<<<grid_mlp, blk>>>(h0, h1, W2, b2, z0, z1,
                                         HDIM, HDIM, 0);
    norm_init_kernel<<<2 * NDIM, 128>>>(z0, z1);
    sim_fused_mma<<<grid_sim, blk, S_SMEM_BYTES>>>(z0, z1, pos);
    loss_kernel<<<1, 256>>>(loss);
}

// round 7
// speedup vs baseline: 1.0035x; 1.0035x over previous
#include <cuda_runtime.h>
#include <math.h>
#include <stdint.h>

// Problem constants
#define NDIM 8192
#define HDIM 512
#define TAU_INV 2.0f     // 1/0.5
#define EPSV 1e-8f

// MLP tiling (unchanged from R5)
constexpr int BM = 128, BN = 128, BK = 32;
constexpr int NTHREADS = 256;

// Sim tiling: block 128x256, 8 warps (2m x 4n), warp tile 64x64, double-buffered
constexpr int SBM = 128, SBN = 256, SBK = 32;
constexpr int S_A_WORDS = 4096;   // 128x32 tf32 per stage
constexpr int S_B_WORDS = 8192;   // 256x32 tf32 per stage
constexpr int S_SMEM_BYTES = (2 * S_A_WORDS + 2 * S_B_WORDS) * 4 + 2 * SBM * 4;

// Scratch (static device memory; no allocation allowed)
__device__ float g_h[2ull * NDIM * HDIM];   // hidden activations (32 MB)
__device__ float g_inv0[NDIM];
__device__ float g_inv1[NDIM];
__device__ float g_S[NDIM];
__device__ float g_P[NDIM];

__device__ __forceinline__ uint32_t f2tf32(float f) {
    uint32_t u;
    asm("cvt.rna.tf32.f32 %0, %1;" : "=r"(u) : "f"(f));
    return u;
}

__device__ __forceinline__ void mma_tf32(float c[4],
                                         const uint32_t a[4],
                                         const uint32_t b[2]) {
    asm volatile(
        "mma.sync.aligned.m16n8k8.row.col.f32.tf32.tf32.f32 "
        "{%0,%1,%2,%3}, {%4,%5,%6,%7}, {%8,%9}, {%0,%1,%2,%3};"
        : "+f"(c[0]), "+f"(c[1]), "+f"(c[2]), "+f"(c[3])
        : "r"(a[0]), "r"(a[1]), "r"(a[2]), "r"(a[3]),
          "r"(b[0]), "r"(b[1]));
}

// ---------------------------------------------------------------------------
// MLP fragment-ordered smem fill (128x32 A, 128x32 B) — unchanged from R5.
// ---------------------------------------------------------------------------
__device__ __forceinline__ void fill_tiles(
    uint32_t* sA, uint32_t* sB,
    const float* __restrict__ A, const float* __restrict__ B,
    int rowBase, int colBase, int K, int k0, int t)
{
#pragma unroll
    for (int v = 0; v < 4; v++) {
        int idx = t + v * 256;
        int row = idx >> 3;
        int q   = idx & 7;
        int ks  = q >> 1;
        int e2  = q & 1;

        float4 va = *reinterpret_cast<const float4*>(
            &A[(size_t)(rowBase + row) * K + k0 + (q << 2)]);
        {
            int mt = row >> 4;
            int rr = row & 15;
            int r  = (rr >> 3) + (e2 << 1);
            uint32_t* p = &sA[(((((mt << 2) + ks) << 5) + ((rr & 7) << 2)) << 2) + r];
            p[0]  = f2tf32(va.x);
            p[4]  = f2tf32(va.y);
            p[8]  = f2tf32(va.z);
            p[12] = f2tf32(va.w);
        }
        float4 vb = *reinterpret_cast<const float4*>(
            &B[(size_t)(colBase + row) * K + k0 + (q << 2)]);
        {
            int nt = row >> 3;
            uint32_t* p = &sB[((((((nt << 2) + ks) << 5) + ((row & 7) << 2))) << 1) + e2];
            p[0] = f2tf32(vb.x);
            p[2] = f2tf32(vb.y);
            p[4] = f2tf32(vb.z);
            p[6] = f2tf32(vb.w);
        }
    }
}

// ---------------------------------------------------------------------------
// MLP GEMM: C = act(A @ B^T + bias), tf32 tensor cores (unchanged from R5).
// ---------------------------------------------------------------------------
__global__ __launch_bounds__(NTHREADS) void gemm_bias_act_mma(
    const float* __restrict__ A0, const float* __restrict__ A1,
    const float* __restrict__ B, const float* __restrict__ bias,
    float* __restrict__ C0, float* __restrict__ C1,
    int K, int Nn, int doElu)
{
    __shared__ uint32_t sA[4096];
    __shared__ uint32_t sB[4096];

    const float* A = (blockIdx.z == 0) ? A0 : A1;
    float* C = (blockIdx.z == 0) ? C0 : C1;

    const int t = threadIdx.x;
    const int wid = t >> 5, lane = t & 31;
    const int wm = wid >> 2, wn = wid & 3;
    const int rowBase = blockIdx.y * BM;
    const int colBase = blockIdx.x * BN;

    float acc[4][4][4];
#pragma unroll
    for (int i = 0; i < 4; i++)
#pragma unroll
        for (int j = 0; j < 4; j++)
#pragma unroll
            for (int r = 0; r < 4; r++) acc[i][j][r] = 0.0f;

    for (int k0 = 0; k0 < K; k0 += BK) {
        fill_tiles(sA, sB, A, B, rowBase, colBase, K, k0, t);
        __syncthreads();

#pragma unroll
        for (int ks = 0; ks < 4; ks++) {
            uint32_t af[4][4];
            uint32_t bf[4][2];
#pragma unroll
            for (int am = 0; am < 4; am++) {
                uint4 v = *reinterpret_cast<const uint4*>(
                    &sA[(((((wm << 2) + am) << 2) + ks) << 5 | lane) << 2]);
                af[am][0] = v.x; af[am][1] = v.y; af[am][2] = v.z; af[am][3] = v.w;
            }
#pragma unroll
            for (int bn = 0; bn < 4; bn++) {
                uint2 v = *reinterpret_cast<const uint2*>(
                    &sB[(((((wn << 2) + bn) << 2) + ks) << 5 | lane) << 1]);
                bf[bn][0] = v.x; bf[bn][1] = v.y;
            }
#pragma unroll
            for (int am = 0; am < 4; am++)
#pragma unroll
                for (int bn = 0; bn < 4; bn++)
                    mma_tf32(acc[am][bn], af[am], bf[bn]);
        }
        __syncthreads();
    }

#pragma unroll
    for (int am = 0; am < 4; am++) {
        int row0 = rowBase + wm * 64 + am * 16 + (lane >> 2);
#pragma unroll
        for (int bn = 0; bn < 4; bn++) {
            int col = colBase + wn * 32 + bn * 8 + ((lane & 3) << 1);
            float b0 = bias[col], b1 = bias[col + 1];
            float v0 = acc[am][bn][0] + b0;
            float v1 = acc[am][bn][1] + b1;
            float v2 = acc[am][bn][2] + b0;
            float v3 = acc[am][bn][3] + b1;
            if (doElu) {
                v0 = (v0 > 0.0f) ? v0 : expm1f(v0);
                v1 = (v1 > 0.0f) ? v1 : expm1f(v1);
                v2 = (v2 > 0.0f) ? v2 : expm1f(v2);
                v3 = (v3 > 0.0f) ? v3 : expm1f(v3);
            }
            float2 lo = {v0, v1}, hi = {v2, v3};
            *reinterpret_cast<float2*>(&C[(size_t)row0 * Nn + col]) = lo;
            *reinterpret_cast<float2*>(&C[(size_t)(row0 + 8) * Nn + col]) = hi;
        }
    }
}

// ---------------------------------------------------------------------------
// Row norms (inverse) + zero the S/P accumulators.
// ---------------------------------------------------------------------------
__global__ void norm_init_kernel(const float* __restrict__ z0,
                                 const float* __restrict__ z1)
{
    int b = blockIdx.x;
    int row = (b < NDIM) ? b : (b - NDIM);
    const float* z = (b < NDIM) ? z0 : z1;

    float4 v = *reinterpret_cast<const float4*>(
        &z[(size_t)row * HDIM + threadIdx.x * 4]);
    float ss = v.x * v.x + v.y * v.y + v.z * v.z + v.w * v.w;
#pragma unroll
    for (int off = 16; off; off >>= 1)
        ss += __shfl_xor_sync(0xffffffffu, ss, off);

    __shared__ float sred[4];
    if ((threadIdx.x & 31) == 0) sred[threadIdx.x >> 5] = ss;
    __syncthreads();
    if (threadIdx.x == 0) {
        float tot = sred[0] + sred[1] + sred[2] + sred[3];
        float inv = 1.0f / sqrtf(tot);
        if (b < NDIM) {
            g_inv0[row] = inv;
            g_S[row] = 0.0f;
            g_P[row] = 0.0f;
        } else {
            g_inv1[row] = inv;
        }
    }
}

// ---------------------------------------------------------------------------
// Fused similarity: block 128x256, warp tile 64x64, double-buffered smem,
// one __syncthreads per k-iter. Epilogue: exp(cos/tau) -> per-row S/P sums.
// ---------------------------------------------------------------------------
__global__ __launch_bounds__(NTHREADS, 1) void sim_fused_mma(
    const float* __restrict__ z0, const float* __restrict__ z1,
    const float* __restrict__ pos)
{
    extern __shared__ uint32_t dynsmem[];
    uint32_t* sA = dynsmem;                         // [2][S_A_WORDS]
    uint32_t* sB = dynsmem + 2 * S_A_WORDS;         // [2][S_B_WORDS]
    float* sS = (float*)(dynsmem + 2 * S_A_WORDS + 2 * S_B_WORDS);
    float* sP = sS + SBM;

    const int t = threadIdx.x;
    const int wid = t >> 5, lane = t & 31;
    const int wm = wid >> 2, wn = wid & 3;          // wm in {0,1}, wn in {0..3}
    const int rowBase = blockIdx.y * SBM;
    const int colBase = blockIdx.x * SBN;
    const int K = HDIM;

    if (t < SBM) { sS[t] = 0.0f; sP[t] = 0.0f; }

    // --- hoisted fill addressing (loop-invariant) ---
    uint32_t offA[4];  const float* gA[4];
    uint32_t offB[8];  const float* gB[8];
#pragma unroll
    for (int v = 0; v < 4; v++) {
        int idx = t + v * 256;
        int row = idx >> 3;
        int q   = idx & 7;
        int ks  = q >> 1;
        int e2  = q & 1;
        int mt = row >> 4;
        int rr = row & 15;
        int r  = (rr >> 3) + (e2 << 1);
        offA[v] = ((((((mt << 2) + ks) << 5) + ((rr & 7) << 2))) << 2) + r;
        gA[v] = &z0[(size_t)(rowBase + row) * K + (q << 2)];
    }
#pragma unroll
    for (int v = 0; v < 8; v++) {
        int idx = t + v * 256;
        int row = idx >> 3;                          // 0..255
        int q   = idx & 7;
        int ks  = q >> 1;
        int e2  = q & 1;
        int nt  = row >> 3;
        offB[v] = ((((((nt << 2) + ks) << 5) + ((row & 7) << 2))) << 1) + e2;
        gB[v] = &z1[(size_t)(colBase + row) * K + (q << 2)];
    }

    float acc[4][8][4];
#pragma unroll
    for (int i = 0; i < 4; i++)
#pragma unroll
        for (int j = 0; j < 8; j++)
#pragma unroll
            for (int r = 0; r < 4; r++) acc[i][j][r] = 0.0f;

    // --- fill stage 0 ---
    {
        uint32_t* dA = sA;
        uint32_t* dB = sB;
#pragma unroll
        for (int v = 0; v < 4; v++) {
            float4 va = *reinterpret_cast<const float4*>(gA[v]);
            uint32_t* p = &dA[offA[v]];
            p[0] = f2tf32(va.x); p[4] = f2tf32(va.y);
            p[8] = f2tf32(va.z); p[12] = f2tf32(va.w);
        }
#pragma unroll
        for (int v = 0; v < 8; v++) {
            float4 vb = *reinterpret_cast<const float4*>(gB[v]);
            uint32_t* p = &dB[offB[v]];
            p[0] = f2tf32(vb.x); p[2] = f2tf32(vb.y);
            p[4] = f2tf32(vb.z); p[6] = f2tf32(vb.w);
        }
    }
    __syncthreads();

    const int NITER = K / SBK;   // 16
    for (int it = 0; it < NITER; it++) {
        const int cur = it & 1;
        const uint32_t* cA = sA + cur * S_A_WORDS;
        const uint32_t* cB = sB + cur * S_B_WORDS;

        // Prefetch+store next stage (different buffer; no hazard with cur reads)
        if (it + 1 < NITER) {
            const int k0n = (it + 1) * SBK;
            uint32_t* dA = sA + (cur ^ 1) * S_A_WORDS;
            uint32_t* dB = sB + (cur ^ 1) * S_B_WORDS;
#pragma unroll
            for (int v = 0; v < 4; v++) {
                float4 va = *reinterpret_cast<const float4*>(gA[v] + k0n);
                uint32_t* p = &dA[offA[v]];
                p[0] = f2tf32(va.x); p[4] = f2tf32(va.y);
                p[8] = f2tf32(va.z); p[12] = f2tf32(va.w);
            }
#pragma unroll
            for (int v = 0; v < 8; v++) {
                float4 vb = *reinterpret_cast<const float4*>(gB[v] + k0n);
                uint32_t* p = &dB[offB[v]];
                p[0] = f2tf32(vb.x); p[2] = f2tf32(vb.y);
                p[4] = f2tf32(vb.z); p[6] = f2tf32(vb.w);
            }
        }

#pragma unroll
        for (int ks = 0; ks < 4; ks++) {
            uint32_t af[4][4];
            uint32_t bf[8][2];
#pragma unroll
            for (int am = 0; am < 4; am++) {
                uint4 v = *reinterpret_cast<const uint4*>(
                    &cA[((((((wm << 2) + am) << 2) + ks) << 5) | lane) << 2]);
                af[am][0] = v.x; af[am][1] = v.y; af[am][2] = v.z; af[am][3] = v.w;
            }
#pragma unroll
            for (int bn = 0; bn < 8; bn++) {
                uint2 v = *reinterpret_cast<const uint2*>(
                    &cB[((((((wn << 3) + bn) << 2) + ks) << 5) | lane) << 1]);
                bf[bn][0] = v.x; bf[bn][1] = v.y;
            }
#pragma unroll
            for (int am = 0; am < 4; am++)
#pragma unroll
                for (int bn = 0; bn < 8; bn++)
                    mma_tf32(acc[am][bn], af[am], bf[bn]);
        }
        __syncthreads();
    }

    // Epilogue: exp(cos/tau), weight by pos, per-row reduce
#pragma unroll
    for (int am = 0; am < 4; am++) {
        int rloc0 = wm * 64 + am * 16 + (lane >> 2);
        int row0 = rowBase + rloc0;
        float ii0 = g_inv0[row0] * TAU_INV;
        float ii1 = g_inv0[row0 + 8] * TAU_INV;
        float s0 = 0.0f, p0 = 0.0f, s1 = 0.0f, p1 = 0.0f;
#pragma unroll
        for (int bn = 0; bn < 8; bn++) {
            int col = colBase + wn * 64 + bn * 8 + ((lane & 3) << 1);
            float j0 = g_inv1[col];
            float j1 = g_inv1[col + 1];
            float2 pv0 = *reinterpret_cast<const float2*>(
                &pos[(size_t)row0 * NDIM + col]);
            float2 pv1 = *reinterpret_cast<const float2*>(
                &pos[(size_t)(row0 + 8) * NDIM + col]);
            float m;
            m = expf(acc[am][bn][0] * ii0 * j0); s0 += m; p0 += m * pv0.x;
            m = expf(acc[am][bn][1] * ii0 * j1); s0 += m; p0 += m * pv0.y;
            m = expf(acc[am][bn][2] * ii1 * j0); s1 += m; p1 += m * pv1.x;
            m = expf(acc[am][bn][3] * ii1 * j1); s1 += m; p1 += m * pv1.y;
        }
#pragma unroll
        for (int off = 1; off < 4; off <<= 1) {
            s0 += __shfl_xor_sync(0xffffffffu, s0, off);
            p0 += __shfl_xor_sync(0xffffffffu, p0, off);
            s1 += __shfl_xor_sync(0xffffffffu, s1, off);
            p1 += __shfl_xor_sync(0xffffffffu, p1, off);
        }
        if ((lane & 3) == 0) {
            atomicAdd(&sS[rloc0], s0);
            atomicAdd(&sP[rloc0], p0);
            atomicAdd(&sS[rloc0 + 8], s1);
            atomicAdd(&sP[rloc0 + 8], p1);
        }
    }
    __syncthreads();
    if (t < SBM) {
        atomicAdd(&g_S[rowBase + t], sS[t]);
        atomicAdd(&g_P[rowBase + t], sP[t]);
    }
}

// ---------------------------------------------------------------------------
// Final loss: -mean(log(P/(S+eps)+eps))
// ---------------------------------------------------------------------------
__global__ void loss_kernel(float* __restrict__ loss_out)
{
    float local = 0.0f;
    for (int i = threadIdx.x; i < NDIM; i += 256) {
        local += logf(g_P[i] / (g_S[i] + EPSV) + EPSV);
    }
#pragma unroll
    for (int off = 16; off; off >>= 1)
        local += __shfl_xor_sync(0xffffffffu, local, off);

    __shared__ float sred[8];
    if ((threadIdx.x & 31) == 0) sred[threadIdx.x >> 5] = local;
    __syncthreads();
    if (threadIdx.x == 0) {
        float tot = 0.0f;
#pragma unroll
        for (int w = 0; w < 8; w++) tot += sred[w];
        loss_out[0] = -tot / (float)NDIM;
    }
}

// ---------------------------------------------------------------------------
// kernel_launch — inputs: embd0, embd1, pos, W1, b1, W2, b2
// output layout: [z0 (N*H) | z1 (N*H) | loss (1)]
// ---------------------------------------------------------------------------
extern "C" void kernel_launch(void* const* d_in, const int* in_sizes, int n_in,
                              void* d_out, int out_size)
{
    const float* embd0 = (const float*)d_in[0];
    const float* embd1 = (const float*)d_in[1];
    const float* pos   = (const float*)d_in[2];
    const float* W1    = (const float*)d_in[3];
    const float* b1    = (const float*)d_in[4];
    const float* W2    = (const float*)d_in[5];
    const float* b2    = (const float*)d_in[6];

    float* out = (float*)d_out;
    float* z0 = out;
    float* z1 = out + (size_t)NDIM * HDIM;
    float* loss = out + 2ull * NDIM * HDIM;

    float* h = nullptr;
    cudaGetSymbolAddress((void**)&h, g_h);
    float* h0 = h;
    float* h1 = h + (size_t)NDIM * HDIM;

    static bool attrDone = false;
    if (!attrDone) {
        cudaFuncSetAttribute(sim_fused_mma,
                             cudaFuncAttributeMaxDynamicSharedMemorySize,
                             S_SMEM_BYTES);
        attrDone = true;
    }

    dim3 blk(NTHREADS);
    dim3 grid_mlp(HDIM / BN, NDIM / BM, 2);     // 4 x 64 x 2
    dim3 grid_sim(NDIM / SBN, NDIM / SBM);      // 32 x 64

    gemm_bias_act_mma<<<grid_mlp, blk>>>(embd0, embd1, W1, b1, h0, h1,
                                         HDIM, HDIM, 1);
    gemm_bias_act_mma<<<grid_mlp, blk>>>(h0, h1, W2, b2, z0, z1,
                                         HDIM, HDIM, 0);
    norm_init_kernel<<<2 * NDIM, 128>>>(z0, z1);
    sim_fused_mma<<<grid_sim, blk, S_SMEM_BYTES>>>(z0, z1, pos);
    loss_kernel<<<1, 256>>>(loss);
}

// round 10
// speedup vs baseline: 1.4153x; 1.4104x over previous
#include <cuda_runtime.h>
#include <cuda_bf16.h>
#include <math.h>
#include <stdint.h>

// Problem constants
#define NDIM 8192
#define HDIM 512
#define TAU_INV 2.0f     // 1/0.5
#define EPSV 1e-8f

// MLP tiling (legacy tf32 mma, unchanged from R5)
constexpr int BM = 128, BN = 128, BK = 32;
constexpr int NTHREADS = 256;

// Sim tiling (bf16 m16n8k16): block 128x256, 8 warps (2m x 4n), warp 64x64,
// BK=32, double-buffered.
constexpr int SBM = 128, SBN = 256, SBK = 32;
constexpr int SA_WORDS = SBM * SBK / 2;   // 2048 uint32 (bf16 pairs) per stage
constexpr int SB_WORDS = SBN * SBK / 2;   // 4096 uint32 per stage
constexpr int SIM_DSMEM = (2 * SA_WORDS + 2 * SB_WORDS) * 4 + 2 * SBM * 4;

// Scratch (static device memory; no allocation allowed)
__device__ float g_h[2ull * NDIM * HDIM];            // hidden activations (32 MB)
__device__ __nv_bfloat16 g_z0b[(size_t)NDIM * HDIM]; // bf16 z0 (8 MB)
__device__ __nv_bfloat16 g_z1b[(size_t)NDIM * HDIM]; // bf16 z1 (8 MB)
__device__ float g_inv0[NDIM];
__device__ float g_inv1[NDIM];
__device__ float g_S[NDIM];
__device__ float g_P[NDIM];

__device__ __forceinline__ uint32_t f2tf32(float f) {
    uint32_t u;
    asm("cvt.rna.tf32.f32 %0, %1;" : "=r"(u) : "f"(f));
    return u;
}

__device__ __forceinline__ void mma_tf32(float c[4],
                                         const uint32_t a[4],
                                         const uint32_t b[2]) {
    asm volatile(
        "mma.sync.aligned.m16n8k8.row.col.f32.tf32.tf32.f32 "
        "{%0,%1,%2,%3}, {%4,%5,%6,%7}, {%8,%9}, {%0,%1,%2,%3};"
        : "+f"(c[0]), "+f"(c[1]), "+f"(c[2]), "+f"(c[3])
        : "r"(a[0]), "r"(a[1]), "r"(a[2]), "r"(a[3]),
          "r"(b[0]), "r"(b[1]));
}

__device__ __forceinline__ void mma_bf16(float c[4],
                                         const uint32_t a[4],
                                         const uint32_t b[2]) {
    asm volatile(
        "mma.sync.aligned.m16n8k16.row.col.f32.bf16.bf16.f32 "
        "{%0,%1,%2,%3}, {%4,%5,%6,%7}, {%8,%9}, {%0,%1,%2,%3};"
        : "+f"(c[0]), "+f"(c[1]), "+f"(c[2]), "+f"(c[3])
        : "r"(a[0]), "r"(a[1]), "r"(a[2]), "r"(a[3]),
          "r"(b[0]), "r"(b[1]));
}

// ---------------------------------------------------------------------------
// MLP fragment-ordered smem fill + GEMM (tf32 mma.sync, unchanged from R5)
// ---------------------------------------------------------------------------
__device__ __forceinline__ void fill_tiles(
    uint32_t* sA, uint32_t* sB,
    const float* __restrict__ A, const float* __restrict__ B,
    int rowBase, int colBase, int K, int k0, int t)
{
#pragma unroll
    for (int v = 0; v < 4; v++) {
        int idx = t + v * 256;
        int row = idx >> 3;
        int q   = idx & 7;
        int ks  = q >> 1;
        int e2  = q & 1;

        float4 va = *reinterpret_cast<const float4*>(
            &A[(size_t)(rowBase + row) * K + k0 + (q << 2)]);
        {
            int mt = row >> 4;
            int rr = row & 15;
            int r  = (rr >> 3) + (e2 << 1);
            uint32_t* p = &sA[(((((mt << 2) + ks) << 5) + ((rr & 7) << 2)) << 2) + r];
            p[0]  = f2tf32(va.x);
            p[4]  = f2tf32(va.y);
            p[8]  = f2tf32(va.z);
            p[12] = f2tf32(va.w);
        }
        float4 vb = *reinterpret_cast<const float4*>(
            &B[(size_t)(colBase + row) * K + k0 + (q << 2)]);
        {
            int nt = row >> 3;
            uint32_t* p = &sB[((((((nt << 2) + ks) << 5) + ((row & 7) << 2))) << 1) + e2];
            p[0] = f2tf32(vb.x);
            p[2] = f2tf32(vb.y);
            p[4] = f2tf32(vb.z);
            p[6] = f2tf32(vb.w);
        }
    }
}

__global__ __launch_bounds__(NTHREADS) void gemm_bias_act_mma(
    const float* __restrict__ A0, const float* __restrict__ A1,
    const float* __restrict__ B, const float* __restrict__ bias,
    float* __restrict__ C0, float* __restrict__ C1,
    int K, int Nn, int doElu)
{
    __shared__ uint32_t sA[4096];
    __shared__ uint32_t sB[4096];

    const float* A = (blockIdx.z == 0) ? A0 : A1;
    float* C = (blockIdx.z == 0) ? C0 : C1;

    const int t = threadIdx.x;
    const int wid = t >> 5, lane = t & 31;
    const int wm = wid >> 2, wn = wid & 3;
    const int rowBase = blockIdx.y * BM;
    const int colBase = blockIdx.x * BN;

    float acc[4][4][4];
#pragma unroll
    for (int i = 0; i < 4; i++)
#pragma unroll
        for (int j = 0; j < 4; j++)
#pragma unroll
            for (int r = 0; r < 4; r++) acc[i][j][r] = 0.0f;

    for (int k0 = 0; k0 < K; k0 += BK) {
        fill_tiles(sA, sB, A, B, rowBase, colBase, K, k0, t);
        __syncthreads();

#pragma unroll
        for (int ks = 0; ks < 4; ks++) {
            uint32_t af[4][4];
            uint32_t bf[4][2];
#pragma unroll
            for (int am = 0; am < 4; am++) {
                uint4 v = *reinterpret_cast<const uint4*>(
                    &sA[(((((wm << 2) + am) << 2) + ks) << 5 | lane) << 2]);
                af[am][0] = v.x; af[am][1] = v.y; af[am][2] = v.z; af[am][3] = v.w;
            }
#pragma unroll
            for (int bn = 0; bn < 4; bn++) {
                uint2 v = *reinterpret_cast<const uint2*>(
                    &sB[(((((wn << 2) + bn) << 2) + ks) << 5 | lane) << 1]);
                bf[bn][0] = v.x; bf[bn][1] = v.y;
            }
#pragma unroll
            for (int am = 0; am < 4; am++)
#pragma unroll
                for (int bn = 0; bn < 4; bn++)
                    mma_tf32(acc[am][bn], af[am], bf[bn]);
        }
        __syncthreads();
    }

#pragma unroll
    for (int am = 0; am < 4; am++) {
        int row0 = rowBase + wm * 64 + am * 16 + (lane >> 2);
#pragma unroll
        for (int bn = 0; bn < 4; bn++) {
            int col = colBase + wn * 32 + bn * 8 + ((lane & 3) << 1);
            float b0 = bias[col], b1 = bias[col + 1];
            float v0 = acc[am][bn][0] + b0;
            float v1 = acc[am][bn][1] + b1;
            float v2 = acc[am][bn][2] + b0;
            float v3 = acc[am][bn][3] + b1;
            if (doElu) {
                v0 = (v0 > 0.0f) ? v0 : expm1f(v0);
                v1 = (v1 > 0.0f) ? v1 : expm1f(v1);
                v2 = (v2 > 0.0f) ? v2 : expm1f(v2);
                v3 = (v3 > 0.0f) ? v3 : expm1f(v3);
            }
            float2 lo = {v0, v1}, hi = {v2, v3};
            *reinterpret_cast<float2*>(&C[(size_t)row0 * Nn + col]) = lo;
            *reinterpret_cast<float2*>(&C[(size_t)(row0 + 8) * Nn + col]) = hi;
        }
    }
}

// ---------------------------------------------------------------------------
// Row norms (inverse) + zero S/P accumulators + emit bf16 copies of z0/z1.
// ---------------------------------------------------------------------------
__global__ void norm_init_kernel(const float* __restrict__ z0,
                                 const float* __restrict__ z1)
{
    int b = blockIdx.x;
    int row = (b < NDIM) ? b : (b - NDIM);
    const float* z = (b < NDIM) ? z0 : z1;
    __nv_bfloat16* zb = (b < NDIM) ? g_z0b : g_z1b;

    float4 v = *reinterpret_cast<const float4*>(
        &z[(size_t)row * HDIM + threadIdx.x * 4]);

    // bf16 copy (8-byte aligned store of 4 bf16)
    __nv_bfloat162 p0 = __floats2bfloat162_rn(v.x, v.y);
    __nv_bfloat162 p1 = __floats2bfloat162_rn(v.z, v.w);
    uint2 packed = { *reinterpret_cast<uint32_t*>(&p0),
                     *reinterpret_cast<uint32_t*>(&p1) };
    *reinterpret_cast<uint2*>(&zb[(size_t)row * HDIM + threadIdx.x * 4]) = packed;

    float ss = v.x * v.x + v.y * v.y + v.z * v.z + v.w * v.w;
#pragma unroll
    for (int off = 16; off; off >>= 1)
        ss += __shfl_xor_sync(0xffffffffu, ss, off);

    __shared__ float sred[4];
    if ((threadIdx.x & 31) == 0) sred[threadIdx.x >> 5] = ss;
    __syncthreads();
    if (threadIdx.x == 0) {
        float tot = sred[0] + sred[1] + sred[2] + sred[3];
        float inv = 1.0f / sqrtf(tot);
        if (b < NDIM) {
            g_inv0[row] = inv;
            g_S[row] = 0.0f;
            g_P[row] = 0.0f;
        } else {
            g_inv1[row] = inv;
        }
    }
}

// ---------------------------------------------------------------------------
// Fused similarity (bf16 m16n8k16 mma): block 128x256, warp 64x64, BK=32,
// double-buffered smem. z tiles read from precomputed bf16 copies.
//
// smem layouts (uint32 = bf16 pair along k):
//  A: sA[((mt*2+ks)*32 + lane)*4 + reg], mt=row/16, ks=k/16,
//     lane=(row%8)*4+((k%8)/2), reg=(row/8)%2 + 2*((k%16)/8)
//  B: sB[((nt*2+ks)*32 + lane)*2 + reg], nt=n/8, ks=k/16,
//     lane=(n%8)*4+((k%8)/2), reg=(k%16)/8
// ---------------------------------------------------------------------------
__global__ __launch_bounds__(NTHREADS, 1) void sim_fused_bf16(
    const float* __restrict__ pos)
{
    extern __shared__ uint32_t dynsmem[];
    uint32_t* sA = dynsmem;                          // [2][SA_WORDS]
    uint32_t* sB = dynsmem + 2 * SA_WORDS;           // [2][SB_WORDS]
    float* sS = (float*)(dynsmem + 2 * SA_WORDS + 2 * SB_WORDS);
    float* sP = sS + SBM;

    const int t = threadIdx.x;
    const int wid = t >> 5, lane = t & 31;
    const int wm = wid >> 2, wn = wid & 3;
    const int rowBase = blockIdx.y * SBM;
    const int colBase = blockIdx.x * SBN;

    if (t < SBM) { sS[t] = 0.0f; sP[t] = 0.0f; }

    // Hoisted fill addressing. Per thread per stage: 2 uint4 for A, 4 for B.
    uint32_t offA[2]; const __nv_bfloat16* gA[2];
    uint32_t offB[4]; const __nv_bfloat16* gB[4];
#pragma unroll
    for (int v = 0; v < 2; v++) {
        int idx = t + v * 256;          // 0..511
        int row = idx >> 2;             // 0..127
        int c   = idx & 3;              // k-chunk of 8 (k = 8c)
        int ks  = c >> 1;
        int hi  = c & 1;
        int mt  = row >> 4;
        int rr  = row & 15;
        offA[v] = (uint32_t)((((mt * 2 + ks) * 32 + (rr & 7) * 4) << 2)
                             + (rr >> 3) + (hi << 1));
        gA[v] = g_z0b + (size_t)(rowBase + row) * HDIM + c * 8;
    }
#pragma unroll
    for (int v = 0; v < 4; v++) {
        int idx = t + v * 256;          // 0..1023
        int n   = idx >> 2;             // 0..255
        int c   = idx & 3;
        int ks  = c >> 1;
        int hi  = c & 1;
        int nt  = n >> 3;
        offB[v] = (uint32_t)((((nt * 2 + ks) * 32 + (n & 7) * 4) << 1) + hi);
        gB[v] = g_z1b + (size_t)(colBase + n) * HDIM + c * 8;
    }

    float acc[4][8][4];
#pragma unroll
    for (int i = 0; i < 4; i++)
#pragma unroll
        for (int j = 0; j < 8; j++)
#pragma unroll
            for (int r = 0; r < 4; r++) acc[i][j][r] = 0.0f;

    // Fill stage 0
    {
        uint32_t* dA = sA;
        uint32_t* dB = sB;
#pragma unroll
        for (int v = 0; v < 2; v++) {
            uint4 w = *reinterpret_cast<const uint4*>(gA[v]);
            uint32_t* p = &dA[offA[v]];
            p[0] = w.x; p[4] = w.y; p[8] = w.z; p[12] = w.w;
        }
#pragma unroll
        for (int v = 0; v < 4; v++) {
            uint4 w = *reinterpret_cast<const uint4*>(gB[v]);
            uint32_t* p = &dB[offB[v]];
            p[0] = w.x; p[2] = w.y; p[4] = w.z; p[6] = w.w;
        }
    }
    __syncthreads();

    const int NITER = HDIM / SBK;   // 16
    for (int it = 0; it < NITER; it++) {
        const int cur = it & 1;
        const uint32_t* cA = sA + cur * SA_WORDS;
        const uint32_t* cB = sB + cur * SB_WORDS;

        if (it + 1 < NITER) {
            const int kn = (it + 1) * SBK;   // bf16 element offset
            uint32_t* dA = sA + (cur ^ 1) * SA_WORDS;
            uint32_t* dB = sB + (cur ^ 1) * SB_WORDS;
#pragma unroll
            for (int v = 0; v < 2; v++) {
                uint4 w = *reinterpret_cast<const uint4*>(gA[v] + kn);
                uint32_t* p = &dA[offA[v]];
                p[0] = w.x; p[4] = w.y; p[8] = w.z; p[12] = w.w;
            }
#pragma unroll
            for (int v = 0; v < 4; v++) {
                uint4 w = *reinterpret_cast<const uint4*>(gB[v] + kn);
                uint32_t* p = &dB[offB[v]];
                p[0] = w.x; p[2] = w.y; p[4] = w.z; p[6] = w.w;
            }
        }

#pragma unroll
        for (int ks = 0; ks < 2; ks++) {
            uint32_t af[4][4];
            uint32_t bf[8][2];
#pragma unroll
            for (int am = 0; am < 4; am++) {
                uint4 v = *reinterpret_cast<const uint4*>(
                    &cA[((((wm * 4 + am) * 2 + ks) * 32 + lane) << 2)]);
                af[am][0] = v.x; af[am][1] = v.y; af[am][2] = v.z; af[am][3] = v.w;
            }
#pragma unroll
            for (int bn = 0; bn < 8; bn++) {
                uint2 v = *reinterpret_cast<const uint2*>(
                    &cB[((((wn * 8 + bn) * 2 + ks) * 32 + lane) << 1)]);
                bf[bn][0] = v.x; bf[bn][1] = v.y;
            }
#pragma unroll
            for (int am = 0; am < 4; am++)
#pragma unroll
                for (int bn = 0; bn < 8; bn++)
                    mma_bf16(acc[am][bn], af[am], bf[bn]);
        }
        __syncthreads();
    }

    // Epilogue: exp(cos/tau), weight by pos, per-row reduce
#pragma unroll
    for (int am = 0; am < 4; am++) {
        int rloc0 = wm * 64 + am * 16 + (lane >> 2);
        int row0 = rowBase + rloc0;
        float ii0 = g_inv0[row0] * TAU_INV;
        float ii1 = g_inv0[row0 + 8] * TAU_INV;
        float s0 = 0.0f, p0 = 0.0f, s1 = 0.0f, p1 = 0.0f;
#pragma unroll
        for (int bn = 0; bn < 8; bn++) {
            int col = colBase + wn * 64 + bn * 8 + ((lane & 3) << 1);
            float j0 = g_inv1[col];
            float j1 = g_inv1[col + 1];
            float2 pv0 = *reinterpret_cast<const float2*>(
                &pos[(size_t)row0 * NDIM + col]);
            float2 pv1 = *reinterpret_cast<const float2*>(
                &pos[(size_t)(row0 + 8) * NDIM + col]);
            float m;
            m = expf(acc[am][bn][0] * ii0 * j0); s0 += m; p0 += m * pv0.x;
            m = expf(acc[am][bn][1] * ii0 * j1); s0 += m; p0 += m * pv0.y;
            m = expf(acc[am][bn][2] * ii1 * j0); s1 += m; p1 += m * pv1.x;
            m = expf(acc[am][bn][3] * ii1 * j1); s1 += m; p1 += m * pv1.y;
        }
#pragma unroll
        for (int off = 1; off < 4; off <<= 1) {
            s0 += __shfl_xor_sync(0xffffffffu, s0, off);
            p0 += __shfl_xor_sync(0xffffffffu, p0, off);
            s1 += __shfl_xor_sync(0xffffffffu, s1, off);
            p1 += __shfl_xor_sync(0xffffffffu, p1, off);
        }
        if ((lane & 3) == 0) {
            atomicAdd(&sS[rloc0], s0);
            atomicAdd(&sP[rloc0], p0);
            atomicAdd(&sS[rloc0 + 8], s1);
            atomicAdd(&sP[rloc0 + 8], p1);
        }
    }
    __syncthreads();
    if (t < SBM) {
        atomicAdd(&g_S[rowBase + t], sS[t]);
        atomicAdd(&g_P[rowBase + t], sP[t]);
    }
}

// ---------------------------------------------------------------------------
// Final loss: -mean(log(P/(S+eps)+eps))
// ---------------------------------------------------------------------------
__global__ void loss_kernel(float* __restrict__ loss_out)
{
    float local = 0.0f;
    for (int i = threadIdx.x; i < NDIM; i += 256) {
        local += logf(g_P[i] / (g_S[i] + EPSV) + EPSV);
    }
#pragma unroll
    for (int off = 16; off; off >>= 1)
        local += __shfl_xor_sync(0xffffffffu, local, off);

    __shared__ float sred[8];
    if ((threadIdx.x & 31) == 0) sred[threadIdx.x >> 5] = local;
    __syncthreads();
    if (threadIdx.x == 0) {
        float tot = 0.0f;
#pragma unroll
        for (int w = 0; w < 8; w++) tot += sred[w];
        loss_out[0] = -tot / (float)NDIM;
    }
}

// ---------------------------------------------------------------------------
// kernel_launch — inputs: embd0, embd1, pos, W1, b1, W2, b2
// output layout: [z0 (N*H) | z1 (N*H) | loss (1)]
// ---------------------------------------------------------------------------
extern "C" void kernel_launch(void* const* d_in, const int* in_sizes, int n_in,
                              void* d_out, int out_size)
{
    const float* embd0 = (const float*)d_in[0];
    const float* embd1 = (const float*)d_in[1];
    const float* pos   = (const float*)d_in[2];
    const float* W1    = (const float*)d_in[3];
    const float* b1    = (const float*)d_in[4];
    const float* W2    = (const float*)d_in[5];
    const float* b2    = (const float*)d_in[6];

    float* out = (float*)d_out;
    float* z0 = out;
    float* z1 = out + (size_t)NDIM * HDIM;
    float* loss = out + 2ull * NDIM * HDIM;

    float* h = nullptr;
    cudaGetSymbolAddress((void**)&h, g_h);
    float* h0 = h;
    float* h1 = h + (size_t)NDIM * HDIM;

    static bool attrDone = false;
    if (!attrDone) {
        cudaFuncSetAttribute(sim_fused_bf16,
                             cudaFuncAttributeMaxDynamicSharedMemorySize,
                             SIM_DSMEM);
        attrDone = true;
    }

    dim3 blk(NTHREADS);
    dim3 grid_mlp(HDIM / BN, NDIM / BM, 2);     // 4 x 64 x 2
    dim3 grid_sim(NDIM / SBN, NDIM / SBM);      // 32 x 64

    gemm_bias_act_mma<<<grid_mlp, blk>>>(embd0, embd1, W1, b1, h0, h1,
                                         HDIM, HDIM, 1);
    gemm_bias_act_mma<<<grid_mlp, blk>>>(h0, h1, W2, b2, z0, z1,
                                         HDIM, HDIM, 0);
    norm_init_kernel<<<2 * NDIM, 128>>>(z0, z1);
    sim_fused_bf16<<<grid_sim, blk, SIM_DSMEM>>>(pos);
    loss_kernel<<<1, 256>>>(loss);
}

// round 11
// speedup vs baseline: 1.4862x; 1.0501x over previous
#include <cuda_runtime.h>
#include <cuda_bf16.h>
#include <math.h>
#include <stdint.h>

// Problem constants
#define NDIM 8192
#define HDIM 512
#define TAU_INV 2.0f     // 1/0.5
#define EPSV 1e-8f

// MLP tiling (tf32 mma, now double-buffered)
constexpr int BM = 128, BN = 128, BK = 32;
constexpr int NTHREADS = 256;
constexpr int MLP_SMEM = 4 * 4096 * 4;     // 2 bufs x (A 4096 + B 4096) words = 64 KB

// Sim tiling (bf16 m16n8k16): block 128x256, warp 64x64, BK=32, double-buffered
constexpr int SBM = 128, SBN = 256, SBK = 32;
constexpr int SA_WORDS = SBM * SBK / 2;   // 2048 uint32 (bf16 pairs) per stage
constexpr int SB_WORDS = SBN * SBK / 2;   // 4096 uint32 per stage
constexpr int SIM_DSMEM = (2 * SA_WORDS + 2 * SB_WORDS) * 4 + 2 * SBM * 4;

// Scratch (static device memory; no allocation allowed)
__device__ float g_h[2ull * NDIM * HDIM];            // hidden activations (32 MB)
__device__ __nv_bfloat16 g_z0b[(size_t)NDIM * HDIM]; // bf16 z0 (8 MB)
__device__ __nv_bfloat16 g_z1b[(size_t)NDIM * HDIM]; // bf16 z1 (8 MB)
__device__ float g_inv0[NDIM];
__device__ float g_inv1[NDIM];
__device__ float g_S[NDIM];
__device__ float g_P[NDIM];

__device__ __forceinline__ uint32_t f2tf32(float f) {
    uint32_t u;
    asm("cvt.rna.tf32.f32 %0, %1;" : "=r"(u) : "f"(f));
    return u;
}

__device__ __forceinline__ void mma_tf32(float c[4],
                                         const uint32_t a[4],
                                         const uint32_t b[2]) {
    asm volatile(
        "mma.sync.aligned.m16n8k8.row.col.f32.tf32.tf32.f32 "
        "{%0,%1,%2,%3}, {%4,%5,%6,%7}, {%8,%9}, {%0,%1,%2,%3};"
        : "+f"(c[0]), "+f"(c[1]), "+f"(c[2]), "+f"(c[3])
        : "r"(a[0]), "r"(a[1]), "r"(a[2]), "r"(a[3]),
          "r"(b[0]), "r"(b[1]));
}

__device__ __forceinline__ void mma_bf16(float c[4],
                                         const uint32_t a[4],
                                         const uint32_t b[2]) {
    asm volatile(
        "mma.sync.aligned.m16n8k16.row.col.f32.bf16.bf16.f32 "
        "{%0,%1,%2,%3}, {%4,%5,%6,%7}, {%8,%9}, {%0,%1,%2,%3};"
        : "+f"(c[0]), "+f"(c[1]), "+f"(c[2]), "+f"(c[3])
        : "r"(a[0]), "r"(a[1]), "r"(a[2]), "r"(a[3]),
          "r"(b[0]), "r"(b[1]));
}

// ---------------------------------------------------------------------------
// MLP GEMM: C = act(A @ B^T + bias), tf32 mma, double-buffered pipeline:
// per iter: LDG(it+1) early -> mma(it) -> STS(it+1) -> sync.
// ---------------------------------------------------------------------------
__global__ __launch_bounds__(NTHREADS, 1) void gemm_bias_act_mma(
    const float* __restrict__ A0, const float* __restrict__ A1,
    const float* __restrict__ B, const float* __restrict__ bias,
    float* __restrict__ C0, float* __restrict__ C1,
    int K, int Nn, int doElu)
{
    extern __shared__ uint32_t msm[];
    uint32_t* sAb[2] = { msm, msm + 4096 };
    uint32_t* sBb[2] = { msm + 8192, msm + 12288 };

    const float* A = (blockIdx.z == 0) ? A0 : A1;
    float* C = (blockIdx.z == 0) ? C0 : C1;

    const int t = threadIdx.x;
    const int wid = t >> 5, lane = t & 31;
    const int wm = wid >> 2, wn = wid & 3;
    const int rowBase = blockIdx.y * BM;
    const int colBase = blockIdx.x * BN;

    // Hoisted fill addressing (fragment-ordered layout, same as before)
    uint32_t offA[4], offB[4];
    const float *gAp[4], *gBp[4];
#pragma unroll
    for (int v = 0; v < 4; v++) {
        int idx = t + v * 256;
        int row = idx >> 3;
        int q   = idx & 7;
        int ks  = q >> 1;
        int e2  = q & 1;
        int mt = row >> 4;
        int rr = row & 15;
        int r  = (rr >> 3) + (e2 << 1);
        offA[v] = (uint32_t)((((((mt << 2) + ks) << 5) + ((rr & 7) << 2)) << 2) + r);
        gAp[v] = A + (size_t)(rowBase + row) * K + (q << 2);
        int nt = row >> 3;
        offB[v] = (uint32_t)((((((nt << 2) + ks) << 5) + ((row & 7) << 2)) << 1) + e2);
        gBp[v] = B + (size_t)(colBase + row) * K + (q << 2);
    }

    float acc[4][4][4];
#pragma unroll
    for (int i = 0; i < 4; i++)
#pragma unroll
        for (int j = 0; j < 4; j++)
#pragma unroll
            for (int r = 0; r < 4; r++) acc[i][j][r] = 0.0f;

    // Prologue: fill buffer 0 with k-chunk 0
    {
#pragma unroll
        for (int v = 0; v < 4; v++) {
            float4 va = *reinterpret_cast<const float4*>(gAp[v]);
            uint32_t* p = &sAb[0][offA[v]];
            p[0]  = f2tf32(va.x); p[4]  = f2tf32(va.y);
            p[8]  = f2tf32(va.z); p[12] = f2tf32(va.w);
            float4 vb = *reinterpret_cast<const float4*>(gBp[v]);
            uint32_t* q2 = &sBb[0][offB[v]];
            q2[0] = f2tf32(vb.x); q2[2] = f2tf32(vb.y);
            q2[4] = f2tf32(vb.z); q2[6] = f2tf32(vb.w);
        }
    }
    __syncthreads();

    const int NITER = K / BK;   // 16
    for (int it = 0; it < NITER; it++) {
        const int cur = it & 1;
        const uint32_t* cA = sAb[cur];
        const uint32_t* cB = sBb[cur];
        const bool pf = (it + 1 < NITER);

        float4 fa[4], fb[4];
        if (pf) {
            const int kn = (it + 1) * BK;
#pragma unroll
            for (int v = 0; v < 4; v++) {
                fa[v] = *reinterpret_cast<const float4*>(gAp[v] + kn);
                fb[v] = *reinterpret_cast<const float4*>(gBp[v] + kn);
            }
        }

#pragma unroll
        for (int ks = 0; ks < 4; ks++) {
            uint32_t af[4][4];
            uint32_t bf[4][2];
#pragma unroll
            for (int am = 0; am < 4; am++) {
                uint4 v = *reinterpret_cast<const uint4*>(
                    &cA[(((((wm << 2) + am) << 2) + ks) << 5 | lane) << 2]);
                af[am][0] = v.x; af[am][1] = v.y; af[am][2] = v.z; af[am][3] = v.w;
            }
#pragma unroll
            for (int bn = 0; bn < 4; bn++) {
                uint2 v = *reinterpret_cast<const uint2*>(
                    &cB[(((((wn << 2) + bn) << 2) + ks) << 5 | lane) << 1]);
                bf[bn][0] = v.x; bf[bn][1] = v.y;
            }
#pragma unroll
            for (int am = 0; am < 4; am++)
#pragma unroll
                for (int bn = 0; bn < 4; bn++)
                    mma_tf32(acc[am][bn], af[am], bf[bn]);
        }

        if (pf) {
            uint32_t* dA = sAb[cur ^ 1];
            uint32_t* dB = sBb[cur ^ 1];
#pragma unroll
            for (int v = 0; v < 4; v++) {
                uint32_t* p = &dA[offA[v]];
                p[0]  = f2tf32(fa[v].x); p[4]  = f2tf32(fa[v].y);
                p[8]  = f2tf32(fa[v].z); p[12] = f2tf32(fa[v].w);
                uint32_t* q2 = &dB[offB[v]];
                q2[0] = f2tf32(fb[v].x); q2[2] = f2tf32(fb[v].y);
                q2[4] = f2tf32(fb[v].z); q2[6] = f2tf32(fb[v].w);
            }
        }
        __syncthreads();
    }

#pragma unroll
    for (int am = 0; am < 4; am++) {
        int row0 = rowBase + wm * 64 + am * 16 + (lane >> 2);
#pragma unroll
        for (int bn = 0; bn < 4; bn++) {
            int col = colBase + wn * 32 + bn * 8 + ((lane & 3) << 1);
            float b0 = bias[col], b1 = bias[col + 1];
            float v0 = acc[am][bn][0] + b0;
            float v1 = acc[am][bn][1] + b1;
            float v2 = acc[am][bn][2] + b0;
            float v3 = acc[am][bn][3] + b1;
            if (doElu) {
                v0 = (v0 > 0.0f) ? v0 : expm1f(v0);
                v1 = (v1 > 0.0f) ? v1 : expm1f(v1);
                v2 = (v2 > 0.0f) ? v2 : expm1f(v2);
                v3 = (v3 > 0.0f) ? v3 : expm1f(v3);
            }
            float2 lo = {v0, v1}, hi = {v2, v3};
            *reinterpret_cast<float2*>(&C[(size_t)row0 * Nn + col]) = lo;
            *reinterpret_cast<float2*>(&C[(size_t)(row0 + 8) * Nn + col]) = hi;
        }
    }
}

// ---------------------------------------------------------------------------
// Row norms (inverse) + zero S/P accumulators + emit bf16 copies of z0/z1.
// ---------------------------------------------------------------------------
__global__ void norm_init_kernel(const float* __restrict__ z0,
                                 const float* __restrict__ z1)
{
    int b = blockIdx.x;
    int row = (b < NDIM) ? b : (b - NDIM);
    const float* z = (b < NDIM) ? z0 : z1;
    __nv_bfloat16* zb = (b < NDIM) ? g_z0b : g_z1b;

    float4 v = *reinterpret_cast<const float4*>(
        &z[(size_t)row * HDIM + threadIdx.x * 4]);

    __nv_bfloat162 p0 = __floats2bfloat162_rn(v.x, v.y);
    __nv_bfloat162 p1 = __floats2bfloat162_rn(v.z, v.w);
    uint2 packed = { *reinterpret_cast<uint32_t*>(&p0),
                     *reinterpret_cast<uint32_t*>(&p1) };
    *reinterpret_cast<uint2*>(&zb[(size_t)row * HDIM + threadIdx.x * 4]) = packed;

    float ss = v.x * v.x + v.y * v.y + v.z * v.z + v.w * v.w;
#pragma unroll
    for (int off = 16; off; off >>= 1)
        ss += __shfl_xor_sync(0xffffffffu, ss, off);

    __shared__ float sred[4];
    if ((threadIdx.x & 31) == 0) sred[threadIdx.x >> 5] = ss;
    __syncthreads();
    if (threadIdx.x == 0) {
        float tot = sred[0] + sred[1] + sred[2] + sred[3];
        float inv = 1.0f / sqrtf(tot);
        if (b < NDIM) {
            g_inv0[row] = inv;
            g_S[row] = 0.0f;
            g_P[row] = 0.0f;
        } else {
            g_inv1[row] = inv;
        }
    }
}

// ---------------------------------------------------------------------------
// Fused similarity (bf16 m16n8k16): block 128x256, warp 64x64, BK=32,
// double-buffered; per iter: LDG(it+1) early -> mma(it) -> STS(it+1) -> sync.
// ---------------------------------------------------------------------------
__global__ __launch_bounds__(NTHREADS, 1) void sim_fused_bf16(
    const float* __restrict__ pos)
{
    extern __shared__ uint32_t dynsmem[];
    uint32_t* sA = dynsmem;                          // [2][SA_WORDS]
    uint32_t* sB = dynsmem + 2 * SA_WORDS;           // [2][SB_WORDS]
    float* sS = (float*)(dynsmem + 2 * SA_WORDS + 2 * SB_WORDS);
    float* sP = sS + SBM;

    const int t = threadIdx.x;
    const int wid = t >> 5, lane = t & 31;
    const int wm = wid >> 2, wn = wid & 3;
    const int rowBase = blockIdx.y * SBM;
    const int colBase = blockIdx.x * SBN;

    if (t < SBM) { sS[t] = 0.0f; sP[t] = 0.0f; }

    // Hoisted fill addressing. Per thread per stage: 2 uint4 (A), 4 uint4 (B).
    uint32_t offA[2]; const __nv_bfloat16* gA[2];
    uint32_t offB[4]; const __nv_bfloat16* gB[4];
#pragma unroll
    for (int v = 0; v < 2; v++) {
        int idx = t + v * 256;          // 0..511
        int row = idx >> 2;             // 0..127
        int c   = idx & 3;              // k-chunk of 8 (k = 8c)
        int ks  = c >> 1;
        int hi  = c & 1;
        int mt  = row >> 4;
        int rr  = row & 15;
        offA[v] = (uint32_t)((((mt * 2 + ks) * 32 + (rr & 7) * 4) << 2)
                             + (rr >> 3) + (hi << 1));
        gA[v] = g_z0b + (size_t)(rowBase + row) * HDIM + c * 8;
    }
#pragma unroll
    for (int v = 0; v < 4; v++) {
        int idx = t + v * 256;          // 0..1023
        int n   = idx >> 2;             // 0..255
        int c   = idx & 3;
        int ks  = c >> 1;
        int hi  = c & 1;
        int nt  = n >> 3;
        offB[v] = (uint32_t)((((nt * 2 + ks) * 32 + (n & 7) * 4) << 1) + hi);
        gB[v] = g_z1b + (size_t)(colBase + n) * HDIM + c * 8;
    }

    float acc[4][8][4];
#pragma unroll
    for (int i = 0; i < 4; i++)
#pragma unroll
        for (int j = 0; j < 8; j++)
#pragma unroll
            for (int r = 0; r < 4; r++) acc[i][j][r] = 0.0f;

    // Prologue: fill stage 0
    {
#pragma unroll
        for (int v = 0; v < 2; v++) {
            uint4 w = *reinterpret_cast<const uint4*>(gA[v]);
            uint32_t* p = &sA[offA[v]];
            p[0] = w.x; p[4] = w.y; p[8] = w.z; p[12] = w.w;
        }
#pragma unroll
        for (int v = 0; v < 4; v++) {
            uint4 w = *reinterpret_cast<const uint4*>(gB[v]);
            uint32_t* p = &sB[offB[v]];
            p[0] = w.x; p[2] = w.y; p[4] = w.z; p[6] = w.w;
        }
    }
    __syncthreads();

    const int NITER = HDIM / SBK;   // 16
    for (int it = 0; it < NITER; it++) {
        const int cur = it & 1;
        const uint32_t* cA = sA + cur * SA_WORDS;
        const uint32_t* cB = sB + cur * SB_WORDS;
        const bool pf = (it + 1 < NITER);

        // Issue next-stage global loads EARLY (no smem consumer yet)
        uint4 wA[2], wB[4];
        if (pf) {
            const int kn = (it + 1) * SBK;
#pragma unroll
            for (int v = 0; v < 2; v++)
                wA[v] = *reinterpret_cast<const uint4*>(gA[v] + kn);
#pragma unroll
            for (int v = 0; v < 4; v++)
                wB[v] = *reinterpret_cast<const uint4*>(gB[v] + kn);
        }

        // mma phase covers the LDG latency
#pragma unroll
        for (int ks = 0; ks < 2; ks++) {
            uint32_t af[4][4];
            uint32_t bf[8][2];
#pragma unroll
            for (int am = 0; am < 4; am++) {
                uint4 v = *reinterpret_cast<const uint4*>(
                    &cA[((((wm * 4 + am) * 2 + ks) * 32 + lane) << 2)]);
                af[am][0] = v.x; af[am][1] = v.y; af[am][2] = v.z; af[am][3] = v.w;
            }
#pragma unroll
            for (int bn = 0; bn < 8; bn++) {
                uint2 v = *reinterpret_cast<const uint2*>(
                    &cB[((((wn * 8 + bn) * 2 + ks) * 32 + lane) << 1)]);
                bf[bn][0] = v.x; bf[bn][1] = v.y;
            }
#pragma unroll
            for (int am = 0; am < 4; am++)
#pragma unroll
                for (int bn = 0; bn < 8; bn++)
                    mma_bf16(acc[am][bn], af[am], bf[bn]);
        }

        // Store next stage (data arrived during mma)
        if (pf) {
            uint32_t* dA = sA + (cur ^ 1) * SA_WORDS;
            uint32_t* dB = sB + (cur ^ 1) * SB_WORDS;
#pragma unroll
            for (int v = 0; v < 2; v++) {
                uint32_t* p = &dA[offA[v]];
                p[0] = wA[v].x; p[4] = wA[v].y; p[8] = wA[v].z; p[12] = wA[v].w;
            }
#pragma unroll
            for (int v = 0; v < 4; v++) {
                uint32_t* p = &dB[offB[v]];
                p[0] = wB[v].x; p[2] = wB[v].y; p[4] = wB[v].z; p[6] = wB[v].w;
            }
        }
        __syncthreads();
    }

    // Epilogue: exp(cos/tau), weight by pos, per-row reduce
#pragma unroll
    for (int am = 0; am < 4; am++) {
        int rloc0 = wm * 64 + am * 16 + (lane >> 2);
        int row0 = rowBase + rloc0;
        float ii0 = g_inv0[row0] * TAU_INV;
        float ii1 = g_inv0[row0 + 8] * TAU_INV;
        float s0 = 0.0f, p0 = 0.0f, s1 = 0.0f, p1 = 0.0f;
#pragma unroll
        for (int bn = 0; bn < 8; bn++) {
            int col = colBase + wn * 64 + bn * 8 + ((lane & 3) << 1);
            float j0 = g_inv1[col];
            float j1 = g_inv1[col + 1];
            float2 pv0 = *reinterpret_cast<const float2*>(
                &pos[(size_t)row0 * NDIM + col]);
            float2 pv1 = *reinterpret_cast<const float2*>(
                &pos[(size_t)(row0 + 8) * NDIM + col]);
            float m;
            m = expf(acc[am][bn][0] * ii0 * j0); s0 += m; p0 += m * pv0.x;
            m = expf(acc[am][bn][1] * ii0 * j1); s0 += m; p0 += m * pv0.y;
            m = expf(acc[am][bn][2] * ii1 * j0); s1 += m; p1 += m * pv1.x;
            m = expf(acc[am][bn][3] * ii1 * j1); s1 += m; p1 += m * pv1.y;
        }
#pragma unroll
        for (int off = 1; off < 4; off <<= 1) {
            s0 += __shfl_xor_sync(0xffffffffu, s0, off);
            p0 += __shfl_xor_sync(0xffffffffu, p0, off);
            s1 += __shfl_xor_sync(0xffffffffu, s1, off);
            p1 += __shfl_xor_sync(0xffffffffu, p1, off);
        }
        if ((lane & 3) == 0) {
            atomicAdd(&sS[rloc0], s0);
            atomicAdd(&sP[rloc0], p0);
            atomicAdd(&sS[rloc0 + 8], s1);
            atomicAdd(&sP[rloc0 + 8], p1);
        }
    }
    __syncthreads();
    if (t < SBM) {
        atomicAdd(&g_S[rowBase + t], sS[t]);
        atomicAdd(&g_P[rowBase + t], sP[t]);
    }
}

// ---------------------------------------------------------------------------
// Final loss: -mean(log(P/(S+eps)+eps))
// ---------------------------------------------------------------------------
__global__ void loss_kernel(float* __restrict__ loss_out)
{
    float local = 0.0f;
    for (int i = threadIdx.x; i < NDIM; i += 256) {
        local += logf(g_P[i] / (g_S[i] + EPSV) + EPSV);
    }
#pragma unroll
    for (int off = 16; off; off >>= 1)
        local += __shfl_xor_sync(0xffffffffu, local, off);

    __shared__ float sred[8];
    if ((threadIdx.x & 31) == 0) sred[threadIdx.x >> 5] = local;
    __syncthreads();
    if (threadIdx.x == 0) {
        float tot = 0.0f;
#pragma unroll
        for (int w = 0; w < 8; w++) tot += sred[w];
        loss_out[0] = -tot / (float)NDIM;
    }
}

// ---------------------------------------------------------------------------
// kernel_launch — inputs: embd0, embd1, pos, W1, b1, W2, b2
// output layout: [z0 (N*H) | z1 (N*H) | loss (1)]
// ---------------------------------------------------------------------------
extern "C" void kernel_launch(void* const* d_in, const int* in_sizes, int n_in,
                              void* d_out, int out_size)
{
    const float* embd0 = (const float*)d_in[0];
    const float* embd1 = (const float*)d_in[1];
    const float* pos   = (const float*)d_in[2];
    const float* W1    = (const float*)d_in[3];
    const float* b1    = (const float*)d_in[4];
    const float* W2    = (const float*)d_in[5];
    const float* b2    = (const float*)d_in[6];

    float* out = (float*)d_out;
    float* z0 = out;
    float* z1 = out + (size_t)NDIM * HDIM;
    float* loss = out + 2ull * NDIM * HDIM;

    float* h = nullptr;
    cudaGetSymbolAddress((void**)&h, g_h);
    float* h0 = h;
    float* h1 = h + (size_t)NDIM * HDIM;

    static bool attrDone = false;
    if (!attrDone) {
        cudaFuncSetAttribute(sim_fused_bf16,
                             cudaFuncAttributeMaxDynamicSharedMemorySize,
                             SIM_DSMEM);
        cudaFuncSetAttribute(gemm_bias_act_mma,
                             cudaFuncAttributeMaxDynamicSharedMemorySize,
                             MLP_SMEM);
        attrDone = true;
    }

    dim3 blk(NTHREADS);
    dim3 grid_mlp(HDIM / BN, NDIM / BM, 2);     // 4 x 64 x 2
    dim3 grid_sim(NDIM / SBN, NDIM / SBM);      // 32 x 64

    gemm_bias_act_mma<<<grid_mlp, blk, MLP_SMEM>>>(embd0, embd1, W1, b1, h0, h1,
                                                   HDIM, HDIM, 1);
    gemm_bias_act_mma<<<grid_mlp, blk, MLP_SMEM>>>(h0, h1, W2, b2, z0, z1,
                                                   HDIM, HDIM, 0);
    norm_init_kernel<<<2 * NDIM, 128>>>(z0, z1);
    sim_fused_bf16<<<grid_sim, blk, SIM_DSMEM>>>(pos);
    loss_kernel<<<1, 256>>>(loss);
}